// round 2
// baseline (speedup 1.0000x reference)
#include <cuda_runtime.h>
#include <math.h>

#define BSZ 1024
#define NS 36336
#define NP 10596

// ---------------- scratch (device globals; no runtime allocation) ----------------
__device__ float g_hs[BSZ * 64];
__device__ float g_hp[BSZ * 64];
__device__ float g_ps[BSZ * NS];          // ~148.8 MB
__device__ float g_pp[BSZ * NP];          // ~43.4 MB
__device__ float g_Ys[BSZ * 20 * 32];
__device__ float g_Yp[BSZ * 20 * 32];
__device__ float g_D1s[BSZ * 16 * 32];
__device__ float g_av[BSZ * 20 * 4];
__device__ float g_xh[BSZ * 16 * 784];    // ~51.4 MB

// ---------------- K1: backbone hidden h = relu(relu(z@w1+b1)@w2+b2) ----------------
__global__ void __launch_bounds__(64) k_backbone(
    const float* __restrict__ z,
    const float* __restrict__ w1, const float* __restrict__ b1,
    const float* __restrict__ w2, const float* __restrict__ b2,
    int sel)
{
    int b = blockIdx.x, t = threadIdx.x;
    __shared__ float zs[32];
    __shared__ float h1[64];
    if (t < 32) zs[t] = z[b * 32 + t];
    __syncthreads();
    float acc = b1[t];
#pragma unroll
    for (int i = 0; i < 32; i++) acc = fmaf(zs[i], w1[i * 64 + t], acc);
    h1[t] = fmaxf(acc, 0.f);
    __syncthreads();
    float acc2 = b2[t];
#pragma unroll
    for (int i = 0; i < 64; i++) acc2 = fmaf(h1[i], w2[i * 64 + t], acc2);
    float* out = sel ? g_hp : g_hs;
    out[b * 64 + t] = fmaxf(acc2, 0.f);
}

// ---------------- K2: materialize per-batch params P = h @ w3 + b3 ----------------
// A (1024x64) x W (64xN) -> P (1024xN). 64x64 tile per block, 4x4 micro-tile.
__global__ void __launch_bounds__(256) k_mat(
    const float* __restrict__ w3, const float* __restrict__ b3, int N, int sel)
{
    const float* h = sel ? g_hp : g_hs;
    float* P = sel ? g_pp : g_ps;
    __shared__ __align__(16) float As[64][68];   // [k][bb], padded
    __shared__ __align__(16) float Bs[64][64];   // [k][nn]
    int n0 = blockIdx.x * 64, b0 = blockIdx.y * 64;
    int tid = threadIdx.x;
    for (int idx = tid; idx < 4096; idx += 256) {
        int bb = idx >> 6, k = idx & 63;
        As[k][bb] = h[(b0 + bb) * 64 + k];
    }
    for (int idx = tid; idx < 4096; idx += 256) {
        int k = idx >> 6, nn = idx & 63;
        int n = n0 + nn;
        Bs[k][nn] = (n < N) ? w3[k * N + n] : 0.f;
    }
    __syncthreads();
    int tx = tid & 15, ty = tid >> 4;
    float acc[4][4] = {};
#pragma unroll
    for (int k = 0; k < 64; k++) {
        float4 av = *(const float4*)&As[k][ty * 4];
        float4 bv = *(const float4*)&Bs[k][tx * 4];
        float ar[4] = {av.x, av.y, av.z, av.w};
        float br[4] = {bv.x, bv.y, bv.z, bv.w};
#pragma unroll
        for (int r = 0; r < 4; r++)
#pragma unroll
            for (int c = 0; c < 4; c++)
                acc[r][c] = fmaf(ar[r], br[c], acc[r][c]);
    }
#pragma unroll
    for (int r = 0; r < 4; r++) {
#pragma unroll
        for (int c = 0; c < 4; c++) {
            int n = n0 + tx * 4 + c;
            if (n < N) P[(size_t)(b0 + ty * 4 + r) * N + n] = acc[r][c] + b3[n];
        }
    }
}

// ---------------- K3: 20-round enc+GRU recurrence, params cached in SMEM ----------------
// 1 block per batch elem. warp0 = s-side, warp1 = p-side. 76544 B dynamic SMEM.
// Per-side layout (base = w*9376 floats):
//   +0 W1(64x32 [i*32+o]) +2048 b1(32) +2080 W2(32x32) +3104 b2(32)
//   +3136 K(32x96 [i*96+o]) +6208 RK(32x96) +9280 bg(96)
// Shared tail @18752: zinit_s(32) zinit_p(32) ein(64) hbuf(64) hold(64) ebuf(64) rhb(64)
__global__ void __launch_bounds__(64) k_recur()
{
    extern __shared__ float sm[];
    int b = blockIdx.x, t = threadIdx.x;
    int w = t >> 5, l = t & 31;
    const float* ps = g_ps + (size_t)b * NS;
    const float* pp = g_pp + (size_t)b * NP;
    for (int i = t; i < 3136; i += 64) sm[i] = ps[i];
    for (int i = t; i < 6240; i += 64) sm[3136 + i] = ps[30064 + i];
    for (int i = t; i < 3136; i += 64) sm[9376 + i] = pp[i];
    for (int i = t; i < 6240; i += 64) sm[12512 + i] = pp[4324 + i];
    if (t < 32) {
        sm[18752 + t] = ps[36304 + t];   // z0_init
        sm[18784 + t] = pp[10564 + t];   // za0_init
    }
    sm[18880 + t] = 0.f;                 // hbuf (ss0, sp0) = 0
    __syncthreads();

    float* ein  = sm + 18816;
    float* hbuf = sm + 18880;
    float* hold = sm + 18944;
    float* ebuf = sm + 19008;
    float* rhb  = sm + 19072;
    const int base = w * 9376;
    float* Yout = (w ? g_Yp : g_Ys) + (size_t)b * 640;

    for (int r = 0; r < 20; r++) {
        int r5 = r % 5;
        float zin;
        if (r == 0 || r5 == 1)      zin = sm[18752 + w * 32 + l];  // init
        else if (r5 == 0)           zin = hold[w * 32 + l];        // prev outer y
        else                        zin = hbuf[w * 32 + l];        // prev round y
        ein[w * 32 + l] = zin;
        __syncthreads();

        // enc1: 64 -> 32, relu
        float a0 = 0, a1 = 0, a2 = 0, a3 = 0;
#pragma unroll
        for (int i = 0; i < 64; i += 4) {
            a0 = fmaf(ein[i],     sm[base + (i)     * 32 + l], a0);
            a1 = fmaf(ein[i + 1], sm[base + (i + 1) * 32 + l], a1);
            a2 = fmaf(ein[i + 2], sm[base + (i + 2) * 32 + l], a2);
            a3 = fmaf(ein[i + 3], sm[base + (i + 3) * 32 + l], a3);
        }
        float e1 = fmaxf(sm[base + 2048 + l] + ((a0 + a1) + (a2 + a3)), 0.f);
        ebuf[w * 32 + l] = e1;
        __syncwarp();

        // enc2: 32 -> 32, no relu
        a0 = a1 = a2 = a3 = 0;
#pragma unroll
        for (int i = 0; i < 32; i += 4) {
            a0 = fmaf(ebuf[w * 32 + i],     sm[base + 2080 + (i)     * 32 + l], a0);
            a1 = fmaf(ebuf[w * 32 + i + 1], sm[base + 2080 + (i + 1) * 32 + l], a1);
            a2 = fmaf(ebuf[w * 32 + i + 2], sm[base + 2080 + (i + 2) * 32 + l], a2);
            a3 = fmaf(ebuf[w * 32 + i + 3], sm[base + 2080 + (i + 3) * 32 + l], a3);
        }
        float e2 = sm[base + 3104 + l] + ((a0 + a1) + (a2 + a3));
        __syncwarp();
        ebuf[w * 32 + l] = e2;
        __syncwarp();

        // GRU gates
        float gz = sm[base + 9280 + l];
        float gr = sm[base + 9280 + 32 + l];
        float gh = sm[base + 9280 + 64 + l];
        float hz = 0.f, hr = 0.f;
#pragma unroll
        for (int i = 0; i < 32; i++) {
            float e  = ebuf[w * 32 + i];
            float hv = hbuf[w * 32 + i];
            gz = fmaf(e,  sm[base + 3136 + i * 96 + l],      gz);
            gr = fmaf(e,  sm[base + 3136 + i * 96 + 32 + l], gr);
            gh = fmaf(e,  sm[base + 3136 + i * 96 + 64 + l], gh);
            hz = fmaf(hv, sm[base + 6208 + i * 96 + l],      hz);
            hr = fmaf(hv, sm[base + 6208 + i * 96 + 32 + l], hr);
        }
        float zgate = 1.f / (1.f + expf(-(gz + hz)));
        float rgate = 1.f / (1.f + expf(-(gr + hr)));
        float hl = hbuf[w * 32 + l];
        rhb[w * 32 + l] = rgate * hl;
        __syncwarp();
        float hh3 = 0.f;
#pragma unroll
        for (int i = 0; i < 32; i++)
            hh3 = fmaf(rhb[w * 32 + i], sm[base + 6208 + i * 96 + 64 + l], hh3);
        float hh = tanhf(gh + hh3);
        float hnew = fmaf(zgate, hl - hh, hh);   // zg*h + (1-zg)*hh
        __syncwarp();
        hbuf[w * 32 + l] = hnew;
        if (r5 == 0) hold[w * 32 + l] = hnew;
        Yout[r * 32 + l] = hnew;
        __syncthreads();
    }
}

// ---------------- K4: dec1 readouts (batched) ----------------
// warp0: s-side dec1 for 16 inner rounds -> g_D1s. warp1: p-side dec1+dec2 -> g_av.
__global__ void __launch_bounds__(64) k_dec()
{
    int b = blockIdx.x, t = threadIdx.x;
    int w = t >> 5, l = t & 31;
    const float* ps = g_ps + (size_t)b * NS;
    const float* pp = g_pp + (size_t)b * NP;
    __shared__ float sW0[1056];   // s dec1 (W 32x32 + b)
    __shared__ float sW1[1056];   // p dec1
    __shared__ float sW2[132];    // p dec2 (W 32x4 + b)
    __shared__ float stmp[32];
    for (int i = t; i < 1056; i += 64) { sW0[i] = ps[3136 + i]; sW1[i] = pp[3136 + i]; }
    for (int i = t; i < 132; i += 64) sW2[i] = pp[4192 + i];
    __syncthreads();

    if (w == 0) {
        for (int m = 0; m < 16; m++) {
            int r = (m >> 2) * 5 + 1 + (m & 3);
            const float* y = g_Ys + (size_t)b * 640 + r * 32;
            float acc = sW0[1024 + l];
#pragma unroll
            for (int i = 0; i < 32; i++) acc = fmaf(y[i], sW0[i * 32 + l], acc);
            g_D1s[(size_t)b * 512 + m * 32 + l] = fmaxf(acc, 0.f);
        }
    } else {
        for (int r = 0; r < 20; r++) {
            const float* y = g_Yp + (size_t)b * 640 + r * 32;
            float acc = sW1[1024 + l];
#pragma unroll
            for (int i = 0; i < 32; i++) acc = fmaf(y[i], sW1[i * 32 + l], acc);
            stmp[l] = fmaxf(acc, 0.f);
            __syncwarp();
            if (l < 4) {
                float a = sW2[128 + l];
#pragma unroll
                for (int i = 0; i < 32; i++) a = fmaf(stmp[i], sW2[i * 4 + l], a);
                g_av[(size_t)b * 80 + r * 4 + l] = a;
            }
            __syncwarp();
        }
    }
}

// ---------------- K5: x_hat = D1s(16x32) @ W2f(32x784) + bias, per batch ----------------
__global__ void __launch_bounds__(256) k_xhat()
{
    int b = blockIdx.x, tid = threadIdx.x;
    const float* ps = g_ps + (size_t)b * NS;
    __shared__ float d1[512];
    for (int i = tid; i < 512; i += 256) d1[i] = g_D1s[(size_t)b * 512 + i];
    __syncthreads();

    float acc[4][16];
#pragma unroll
    for (int q = 0; q < 4; q++) {
        int o = tid + 256 * q;
        float bias = (o < 784) ? ps[29280 + o] : 0.f;
#pragma unroll
        for (int m = 0; m < 16; m++) acc[q][m] = bias;
    }
#pragma unroll 4
    for (int j = 0; j < 32; j++) {
        const float* wrow = ps + 4192 + j * 784;
        float w0 = wrow[tid];
        float w1 = wrow[tid + 256];
        float w2 = wrow[tid + 512];
        float w3v = (tid < 16) ? wrow[tid + 768] : 0.f;
#pragma unroll
        for (int m = 0; m < 16; m++) {
            float dv = d1[m * 32 + j];
            acc[0][m] = fmaf(dv, w0, acc[0][m]);
            acc[1][m] = fmaf(dv, w1, acc[1][m]);
            acc[2][m] = fmaf(dv, w2, acc[2][m]);
            acc[3][m] = fmaf(dv, w3v, acc[3][m]);
        }
    }
    float* xh = g_xh + (size_t)b * 12544;
#pragma unroll
    for (int q = 0; q < 4; q++) {
        int o = tid + 256 * q;
        if (o < 784) {
#pragma unroll
            for (int m = 0; m < 16; m++) xh[m * 784 + o] = acc[q][m];
        }
    }
}

// ---------------- K6: inner + outer bilinear composite ----------------
__device__ __forceinline__ float bsample(const float* img, float a0, float a1,
                                         float a2, float a3, int i, int j)
{
    float sx = a0 + 1.f, sy = a1 + 1.f;
    float gx = -1.f + j * (2.f / 27.f);
    float gy = -1.f + i * (2.f / 27.f);
    float px = (fmaf(sx, gx, a2) + 1.f) * 13.5f;
    float py = (fmaf(sy, gy, a3) + 1.f) * 13.5f;
    float x0 = floorf(px), y0 = floorf(py);
    float wx = px - x0, wy = py - y0;
    int xi = (int)x0, yi = (int)y0;
    float v00 = (yi >= 0 && yi < 28 && xi >= 0 && xi < 28)         ? img[yi * 28 + xi]           : 0.f;
    float v01 = (yi >= 0 && yi < 28 && xi + 1 >= 0 && xi + 1 < 28) ? img[yi * 28 + xi + 1]       : 0.f;
    float v10 = (yi + 1 >= 0 && yi + 1 < 28 && xi >= 0 && xi < 28) ? img[(yi + 1) * 28 + xi]     : 0.f;
    float v11 = (yi + 1 >= 0 && yi + 1 < 28 && xi + 1 >= 0 && xi + 1 < 28) ? img[(yi + 1) * 28 + xi + 1] : 0.f;
    return v00 * (1.f - wx) * (1.f - wy) + v01 * wx * (1.f - wy)
         + v10 * (1.f - wx) * wy + v11 * wx * wy;
}

__global__ void __launch_bounds__(256) k_compose(float* __restrict__ out)
{
    extern __shared__ float s[];
    float* xh = s;            // 12544
    float* Oi = s + 12544;    // 3136
    float* av = s + 15680;    // 80
    int b = blockIdx.x, tid = threadIdx.x;
    const float* gxh = g_xh + (size_t)b * 12544;
    for (int i = tid; i < 12544; i += 256) xh[i] = gxh[i];
    if (tid < 80) av[tid] = g_av[(size_t)b * 80 + tid];
    __syncthreads();

    for (int tt = 0; tt < 4; tt++) {
        for (int p = tid; p < 784; p += 256) {
            int i = p / 28, j = p % 28;
            float acc = 0.f;
#pragma unroll
            for (int u = 0; u < 4; u++) {
                const float* ai = av + (5 * tt + 1 + u) * 4;
                acc += bsample(xh + (4 * tt + u) * 784, ai[0], ai[1], ai[2], ai[3], i, j);
            }
            Oi[tt * 784 + p] = acc;
        }
    }
    __syncthreads();
    for (int p = tid; p < 784; p += 256) {
        int i = p / 28, j = p % 28;
        float acc = 0.f;
#pragma unroll
        for (int tt = 0; tt < 4; tt++) {
            const float* ao = av + 5 * tt * 4;
            acc += bsample(Oi + tt * 784, ao[0], ao[1], ao[2], ao[3], i, j);
        }
        out[(size_t)b * 784 + p] = acc;
    }
}

// ---------------- launch ----------------
extern "C" void kernel_launch(void* const* d_in, const int* in_sizes, int n_in,
                              void* d_out, int out_size)
{
    (void)in_sizes; (void)n_in;
    const float* z    = (const float*)d_in[1];
    const float* s_w1 = (const float*)d_in[2];
    const float* s_b1 = (const float*)d_in[3];
    const float* s_w2 = (const float*)d_in[4];
    const float* s_b2 = (const float*)d_in[5];
    const float* s_w3 = (const float*)d_in[6];
    const float* s_b3 = (const float*)d_in[7];
    const float* p_w1 = (const float*)d_in[8];
    const float* p_b1 = (const float*)d_in[9];
    const float* p_w2 = (const float*)d_in[10];
    const float* p_b2 = (const float*)d_in[11];
    const float* p_w3 = (const float*)d_in[12];
    const float* p_b3 = (const float*)d_in[13];
    float* out = (float*)d_out;

    cudaFuncSetAttribute(k_recur, cudaFuncAttributeMaxDynamicSharedMemorySize, 76544);
    cudaFuncSetAttribute(k_compose, cudaFuncAttributeMaxDynamicSharedMemorySize, 63040);

    k_backbone<<<BSZ, 64>>>(z, s_w1, s_b1, s_w2, s_b2, 0);
    k_backbone<<<BSZ, 64>>>(z, p_w1, p_b1, p_w2, p_b2, 1);
    k_mat<<<dim3((NS + 63) / 64, BSZ / 64), 256>>>(s_w3, s_b3, NS, 0);
    k_mat<<<dim3((NP + 63) / 64, BSZ / 64), 256>>>(p_w3, p_b3, NP, 1);
    k_recur<<<BSZ, 64, 76544>>>();
    k_dec<<<BSZ, 64>>>();
    k_xhat<<<BSZ, 256>>>();
    k_compose<<<BSZ, 256, 63040>>>(out);
}

// round 3
// speedup vs baseline: 1.4298x; 1.4298x over previous
#include <cuda_runtime.h>
#include <math.h>

#define BSZ 1024
#define NS 36336
#define NP 10596

// ---------------- scratch (device globals; no runtime allocation) ----------------
__device__ float g_hs[BSZ * 64];
__device__ float g_hp[BSZ * 64];
__device__ float g_ps[BSZ * NS];          // ~148.8 MB
__device__ float g_pp[BSZ * NP];          // ~43.4 MB
__device__ float g_Ys[BSZ * 20 * 32];
__device__ float g_Yp[BSZ * 20 * 32];
__device__ float g_D1s[BSZ * 16 * 32];
__device__ float g_av[BSZ * 20 * 4];
__device__ float g_xh[BSZ * 16 * 784];    // ~51.4 MB

// ---------------- K1: backbone hidden h = relu(relu(z@w1+b1)@w2+b2) ----------------
__global__ void __launch_bounds__(64) k_backbone(
    const float* __restrict__ z,
    const float* __restrict__ w1, const float* __restrict__ b1,
    const float* __restrict__ w2, const float* __restrict__ b2,
    int sel)
{
    int b = blockIdx.x, t = threadIdx.x;
    __shared__ float zs[32];
    __shared__ float h1[64];
    if (t < 32) zs[t] = z[b * 32 + t];
    __syncthreads();
    float acc = b1[t];
#pragma unroll
    for (int i = 0; i < 32; i++) acc = fmaf(zs[i], w1[i * 64 + t], acc);
    h1[t] = fmaxf(acc, 0.f);
    __syncthreads();
    float acc2 = b2[t];
#pragma unroll
    for (int i = 0; i < 64; i++) acc2 = fmaf(h1[i], w2[i * 64 + t], acc2);
    float* out = sel ? g_hp : g_hs;
    out[b * 64 + t] = fmaxf(acc2, 0.f);
}

// ---------------- K2: materialize per-batch params P = h @ w3 + b3 ----------------
// A (1024x64) x W (64xN) -> P (1024xN).
// 128x128 tile / block, 256 threads, 8x8 micro-tile, strided fragments.
// K=64 fits in one SMEM stage (no k-tile loop). Dynamic SMEM = 65792 B.
__global__ void __launch_bounds__(256) k_mat(
    const float* __restrict__ w3, const float* __restrict__ b3, int N, int sel)
{
    extern __shared__ float smx[];
    float* As = smx;              // [64][129] padded: conflict-free transpose store
    float* Bs = smx + 64 * 129;   // [64][128]
    const float* h = sel ? g_hp : g_hs;
    float* P = sel ? g_pp : g_ps;
    int n0 = blockIdx.x * 128, b0 = blockIdx.y * 128;
    int tid = threadIdx.x;

    // stage A: 128 batches x 64 k (read coalesced over k, store transposed)
#pragma unroll
    for (int it = 0; it < 32; it++) {
        int idx = tid + 256 * it;
        int bb = idx >> 6, k = idx & 63;
        As[k * 129 + bb] = h[(b0 + bb) * 64 + k];
    }
    // stage B: 64 k x 128 n (coalesced)
#pragma unroll
    for (int it = 0; it < 32; it++) {
        int idx = tid + 256 * it;
        int k = idx >> 7, nn = idx & 127;
        int n = n0 + nn;
        Bs[k * 128 + nn] = (n < N) ? w3[(size_t)k * N + n] : 0.f;
    }
    __syncthreads();

    int tx = tid & 15, ty = tid >> 4;
    float acc[8][8] = {};
#pragma unroll 4
    for (int k = 0; k < 64; k++) {
        float a[8], bf[8];
#pragma unroll
        for (int r = 0; r < 8; r++) a[r] = As[k * 129 + ty + 16 * r];
#pragma unroll
        for (int c = 0; c < 8; c++) bf[c] = Bs[k * 128 + tx + 16 * c];
#pragma unroll
        for (int r = 0; r < 8; r++)
#pragma unroll
            for (int c = 0; c < 8; c++)
                acc[r][c] = fmaf(a[r], bf[c], acc[r][c]);
    }

    float bias[8];
#pragma unroll
    for (int c = 0; c < 8; c++) {
        int n = n0 + tx + 16 * c;
        bias[c] = (n < N) ? b3[n] : 0.f;
    }
#pragma unroll
    for (int r = 0; r < 8; r++) {
        size_t row = (size_t)(b0 + ty + 16 * r) * N;
#pragma unroll
        for (int c = 0; c < 8; c++) {
            int n = n0 + tx + 16 * c;
            if (n < N) P[row + n] = acc[r][c] + bias[c];
        }
    }
}

// ---------------- K3: 20-round enc+GRU recurrence, params cached in SMEM ----------------
// 1 block per batch elem. 128 threads: warps 2-3 help stage params (float4), then idle.
// warp0 = s-side, warp1 = p-side compute. 76544 B dynamic SMEM.
// Per-side layout (base = w*9376 floats):
//   +0 W1(64x32 [i*32+o]) +2048 b1(32) +2080 W2(32x32) +3104 b2(32)
//   +3136 K(32x96 [i*96+o]) +6208 RK(32x96) +9280 bg(96)
// Shared tail @18752: zinit_s(32) zinit_p(32) ein(64) hbuf(64) hold(64) ebuf(64) rhb(64)
__global__ void __launch_bounds__(128) k_recur()
{
    extern __shared__ float sm[];
    int b = blockIdx.x, t = threadIdx.x;
    int w = t >> 5, l = t & 31;
    const float* ps = g_ps + (size_t)b * NS;
    const float* pp = g_pp + (size_t)b * NP;
    // vectorized staging (all offsets 16B-aligned)
    for (int i = t; i < 784; i += 128)
        ((float4*)sm)[i] = ((const float4*)ps)[i];
    for (int i = t; i < 1560; i += 128)
        ((float4*)(sm + 3136))[i] = *(const float4*)(ps + 30064 + i * 4);
    for (int i = t; i < 784; i += 128)
        ((float4*)(sm + 9376))[i] = ((const float4*)pp)[i];
    for (int i = t; i < 1560; i += 128)
        ((float4*)(sm + 12512))[i] = *(const float4*)(pp + 4324 + i * 4);
    if (t < 32) {
        sm[18752 + t] = ps[36304 + t];   // z0_init
        sm[18784 + t] = pp[10564 + t];   // za0_init
    }
    if (t < 64) sm[18880 + t] = 0.f;     // hbuf (ss0, sp0) = 0
    __syncthreads();

    float* ein  = sm + 18816;
    float* hbuf = sm + 18880;
    float* hold = sm + 18944;
    float* ebuf = sm + 19008;
    float* rhb  = sm + 19072;
    const int base = w * 9376;
    float* Yout = (w ? g_Yp : g_Ys) + (size_t)b * 640;

    for (int r = 0; r < 20; r++) {
        int r5 = r % 5;
        if (t < 64) {
            float zin;
            if (r == 0 || r5 == 1)      zin = sm[18752 + w * 32 + l];  // init
            else if (r5 == 0)           zin = hold[w * 32 + l];        // prev outer y
            else                        zin = hbuf[w * 32 + l];        // prev round y
            ein[w * 32 + l] = zin;
        }
        __syncthreads();

        if (t < 64) {
            // enc1: 64 -> 32, relu
            float a0 = 0, a1 = 0, a2 = 0, a3 = 0;
#pragma unroll
            for (int i = 0; i < 64; i += 4) {
                a0 = fmaf(ein[i],     sm[base + (i)     * 32 + l], a0);
                a1 = fmaf(ein[i + 1], sm[base + (i + 1) * 32 + l], a1);
                a2 = fmaf(ein[i + 2], sm[base + (i + 2) * 32 + l], a2);
                a3 = fmaf(ein[i + 3], sm[base + (i + 3) * 32 + l], a3);
            }
            float e1 = fmaxf(sm[base + 2048 + l] + ((a0 + a1) + (a2 + a3)), 0.f);
            ebuf[w * 32 + l] = e1;
            __syncwarp();

            // enc2: 32 -> 32, no relu
            a0 = a1 = a2 = a3 = 0;
#pragma unroll
            for (int i = 0; i < 32; i += 4) {
                a0 = fmaf(ebuf[w * 32 + i],     sm[base + 2080 + (i)     * 32 + l], a0);
                a1 = fmaf(ebuf[w * 32 + i + 1], sm[base + 2080 + (i + 1) * 32 + l], a1);
                a2 = fmaf(ebuf[w * 32 + i + 2], sm[base + 2080 + (i + 2) * 32 + l], a2);
                a3 = fmaf(ebuf[w * 32 + i + 3], sm[base + 2080 + (i + 3) * 32 + l], a3);
            }
            float e2 = sm[base + 3104 + l] + ((a0 + a1) + (a2 + a3));
            __syncwarp();
            ebuf[w * 32 + l] = e2;
            __syncwarp();

            // GRU gates
            float gz = sm[base + 9280 + l];
            float gr = sm[base + 9280 + 32 + l];
            float gh = sm[base + 9280 + 64 + l];
            float hz = 0.f, hr = 0.f;
#pragma unroll
            for (int i = 0; i < 32; i++) {
                float e  = ebuf[w * 32 + i];
                float hv = hbuf[w * 32 + i];
                gz = fmaf(e,  sm[base + 3136 + i * 96 + l],      gz);
                gr = fmaf(e,  sm[base + 3136 + i * 96 + 32 + l], gr);
                gh = fmaf(e,  sm[base + 3136 + i * 96 + 64 + l], gh);
                hz = fmaf(hv, sm[base + 6208 + i * 96 + l],      hz);
                hr = fmaf(hv, sm[base + 6208 + i * 96 + 32 + l], hr);
            }
            float zgate = 1.f / (1.f + expf(-(gz + hz)));
            float rgate = 1.f / (1.f + expf(-(gr + hr)));
            float hl = hbuf[w * 32 + l];
            rhb[w * 32 + l] = rgate * hl;
            __syncwarp();
            float hh3 = 0.f;
#pragma unroll
            for (int i = 0; i < 32; i++)
                hh3 = fmaf(rhb[w * 32 + i], sm[base + 6208 + i * 96 + 64 + l], hh3);
            float hh = tanhf(gh + hh3);
            float hnew = fmaf(zgate, hl - hh, hh);   // zg*h + (1-zg)*hh
            __syncwarp();
            hbuf[w * 32 + l] = hnew;
            if (r5 == 0) hold[w * 32 + l] = hnew;
            Yout[r * 32 + l] = hnew;
        }
        __syncthreads();
    }
}

// ---------------- K4: dec1 readouts (batched) ----------------
// warp0: s-side dec1 for 16 inner rounds -> g_D1s. warp1: p-side dec1+dec2 -> g_av.
__global__ void __launch_bounds__(64) k_dec()
{
    int b = blockIdx.x, t = threadIdx.x;
    int w = t >> 5, l = t & 31;
    const float* ps = g_ps + (size_t)b * NS;
    const float* pp = g_pp + (size_t)b * NP;
    __shared__ float sW0[1056];   // s dec1 (W 32x32 + b)
    __shared__ float sW1[1056];   // p dec1
    __shared__ float sW2[132];    // p dec2 (W 32x4 + b)
    __shared__ float stmp[32];
    for (int i = t; i < 1056; i += 64) { sW0[i] = ps[3136 + i]; sW1[i] = pp[3136 + i]; }
    for (int i = t; i < 132; i += 64) sW2[i] = pp[4192 + i];
    __syncthreads();

    if (w == 0) {
        for (int m = 0; m < 16; m++) {
            int r = (m >> 2) * 5 + 1 + (m & 3);
            const float* y = g_Ys + (size_t)b * 640 + r * 32;
            float acc = sW0[1024 + l];
#pragma unroll
            for (int i = 0; i < 32; i++) acc = fmaf(y[i], sW0[i * 32 + l], acc);
            g_D1s[(size_t)b * 512 + m * 32 + l] = fmaxf(acc, 0.f);
        }
    } else {
        for (int r = 0; r < 20; r++) {
            const float* y = g_Yp + (size_t)b * 640 + r * 32;
            float acc = sW1[1024 + l];
#pragma unroll
            for (int i = 0; i < 32; i++) acc = fmaf(y[i], sW1[i * 32 + l], acc);
            stmp[l] = fmaxf(acc, 0.f);
            __syncwarp();
            if (l < 4) {
                float a = sW2[128 + l];
#pragma unroll
                for (int i = 0; i < 32; i++) a = fmaf(stmp[i], sW2[i * 4 + l], a);
                g_av[(size_t)b * 80 + r * 4 + l] = a;
            }
            __syncwarp();
        }
    }
}

// ---------------- K5: x_hat = D1s(16x32) @ W2f(32x784) + bias, per batch ----------------
__global__ void __launch_bounds__(256) k_xhat()
{
    int b = blockIdx.x, tid = threadIdx.x;
    const float* ps = g_ps + (size_t)b * NS;
    __shared__ float d1[512];
    for (int i = tid; i < 512; i += 256) d1[i] = g_D1s[(size_t)b * 512 + i];
    __syncthreads();

    float acc[4][16];
#pragma unroll
    for (int q = 0; q < 4; q++) {
        int o = tid + 256 * q;
        float bias = (o < 784) ? ps[29280 + o] : 0.f;
#pragma unroll
        for (int m = 0; m < 16; m++) acc[q][m] = bias;
    }
#pragma unroll 4
    for (int j = 0; j < 32; j++) {
        const float* wrow = ps + 4192 + j * 784;
        float w0 = wrow[tid];
        float w1 = wrow[tid + 256];
        float w2 = wrow[tid + 512];
        float w3v = (tid < 16) ? wrow[tid + 768] : 0.f;
#pragma unroll
        for (int m = 0; m < 16; m++) {
            float dv = d1[m * 32 + j];
            acc[0][m] = fmaf(dv, w0, acc[0][m]);
            acc[1][m] = fmaf(dv, w1, acc[1][m]);
            acc[2][m] = fmaf(dv, w2, acc[2][m]);
            acc[3][m] = fmaf(dv, w3v, acc[3][m]);
        }
    }
    float* xh = g_xh + (size_t)b * 12544;
#pragma unroll
    for (int q = 0; q < 4; q++) {
        int o = tid + 256 * q;
        if (o < 784) {
#pragma unroll
            for (int m = 0; m < 16; m++) xh[m * 784 + o] = acc[q][m];
        }
    }
}

// ---------------- K6: inner + outer bilinear composite ----------------
__device__ __forceinline__ float bsample(const float* img, float a0, float a1,
                                         float a2, float a3, int i, int j)
{
    float sx = a0 + 1.f, sy = a1 + 1.f;
    float gx = -1.f + j * (2.f / 27.f);
    float gy = -1.f + i * (2.f / 27.f);
    float px = (fmaf(sx, gx, a2) + 1.f) * 13.5f;
    float py = (fmaf(sy, gy, a3) + 1.f) * 13.5f;
    float x0 = floorf(px), y0 = floorf(py);
    float wx = px - x0, wy = py - y0;
    int xi = (int)x0, yi = (int)y0;
    float v00 = (yi >= 0 && yi < 28 && xi >= 0 && xi < 28)         ? img[yi * 28 + xi]           : 0.f;
    float v01 = (yi >= 0 && yi < 28 && xi + 1 >= 0 && xi + 1 < 28) ? img[yi * 28 + xi + 1]       : 0.f;
    float v10 = (yi + 1 >= 0 && yi + 1 < 28 && xi >= 0 && xi < 28) ? img[(yi + 1) * 28 + xi]     : 0.f;
    float v11 = (yi + 1 >= 0 && yi + 1 < 28 && xi + 1 >= 0 && xi + 1 < 28) ? img[(yi + 1) * 28 + xi + 1] : 0.f;
    return v00 * (1.f - wx) * (1.f - wy) + v01 * wx * (1.f - wy)
         + v10 * (1.f - wx) * wy + v11 * wx * wy;
}

__global__ void __launch_bounds__(256) k_compose(float* __restrict__ out)
{
    extern __shared__ float s[];
    float* xh = s;            // 12544
    float* Oi = s + 12544;    // 3136
    float* av = s + 15680;    // 80
    int b = blockIdx.x, tid = threadIdx.x;
    const float* gxh = g_xh + (size_t)b * 12544;
    for (int i = tid; i < 3136; i += 256)
        ((float4*)xh)[i] = ((const float4*)gxh)[i];
    if (tid < 80) av[tid] = g_av[(size_t)b * 80 + tid];
    __syncthreads();

    for (int tt = 0; tt < 4; tt++) {
        for (int p = tid; p < 784; p += 256) {
            int i = p / 28, j = p % 28;
            float acc = 0.f;
#pragma unroll
            for (int u = 0; u < 4; u++) {
                const float* ai = av + (5 * tt + 1 + u) * 4;
                acc += bsample(xh + (4 * tt + u) * 784, ai[0], ai[1], ai[2], ai[3], i, j);
            }
            Oi[tt * 784 + p] = acc;
        }
    }
    __syncthreads();
    for (int p = tid; p < 784; p += 256) {
        int i = p / 28, j = p % 28;
        float acc = 0.f;
#pragma unroll
        for (int tt = 0; tt < 4; tt++) {
            const float* ao = av + 5 * tt * 4;
            acc += bsample(Oi + tt * 784, ao[0], ao[1], ao[2], ao[3], i, j);
        }
        out[(size_t)b * 784 + p] = acc;
    }
}

// ---------------- launch ----------------
extern "C" void kernel_launch(void* const* d_in, const int* in_sizes, int n_in,
                              void* d_out, int out_size)
{
    (void)in_sizes; (void)n_in;
    const float* z    = (const float*)d_in[1];
    const float* s_w1 = (const float*)d_in[2];
    const float* s_b1 = (const float*)d_in[3];
    const float* s_w2 = (const float*)d_in[4];
    const float* s_b2 = (const float*)d_in[5];
    const float* s_w3 = (const float*)d_in[6];
    const float* s_b3 = (const float*)d_in[7];
    const float* p_w1 = (const float*)d_in[8];
    const float* p_b1 = (const float*)d_in[9];
    const float* p_w2 = (const float*)d_in[10];
    const float* p_b2 = (const float*)d_in[11];
    const float* p_w3 = (const float*)d_in[12];
    const float* p_b3 = (const float*)d_in[13];
    float* out = (float*)d_out;

    cudaFuncSetAttribute(k_mat, cudaFuncAttributeMaxDynamicSharedMemorySize, 65792);
    cudaFuncSetAttribute(k_recur, cudaFuncAttributeMaxDynamicSharedMemorySize, 76544);
    cudaFuncSetAttribute(k_compose, cudaFuncAttributeMaxDynamicSharedMemorySize, 63040);

    k_backbone<<<BSZ, 64>>>(z, s_w1, s_b1, s_w2, s_b2, 0);
    k_backbone<<<BSZ, 64>>>(z, p_w1, p_b1, p_w2, p_b2, 1);
    k_mat<<<dim3((NS + 127) / 128, BSZ / 128), 256, 65792>>>(s_w3, s_b3, NS, 0);
    k_mat<<<dim3((NP + 127) / 128, BSZ / 128), 256, 65792>>>(p_w3, p_b3, NP, 1);
    k_recur<<<BSZ, 128, 76544>>>();
    k_dec<<<BSZ, 64>>>();
    k_xhat<<<BSZ, 256>>>();
    k_compose<<<BSZ, 256, 63040>>>(out);
}

// round 6
// speedup vs baseline: 1.7418x; 1.2183x over previous
#include <cuda_runtime.h>
#include <cuda_bf16.h>
#include <cstdint>
#include <math.h>

#define BSZ 1024
#define NS 36336
#define NP 10596

// ---------------- scratch (device globals; no runtime allocation) ----------------
__device__ float g_hs[BSZ * 64];
__device__ float g_hp[BSZ * 64];
__device__ float g_ps[BSZ * NS];          // ~148.8 MB
__device__ float g_pp[BSZ * NP];          // ~43.4 MB
__device__ float g_Ys[BSZ * 20 * 32];
__device__ float g_Yp[BSZ * 20 * 32];
__device__ float g_D1s[BSZ * 16 * 32];
__device__ float g_av[BSZ * 20 * 4];
__device__ float g_xh[BSZ * 16 * 784];    // ~51.4 MB

__device__ __forceinline__ uint32_t smem_u32(const void* p) {
    uint32_t a;
    asm("{ .reg .u64 t; cvta.to.shared.u64 t, %1; cvt.u32.u64 %0, t; }" : "=r"(a) : "l"(p));
    return a;
}
__device__ __forceinline__ void ldm_x4(uint32_t& r0, uint32_t& r1, uint32_t& r2, uint32_t& r3,
                                       uint32_t addr) {
    asm volatile("ldmatrix.sync.aligned.m8n8.x4.shared.b16 {%0,%1,%2,%3}, [%4];"
                 : "=r"(r0), "=r"(r1), "=r"(r2), "=r"(r3) : "r"(addr));
}
__device__ __forceinline__ void mma_bf16(float* d, const uint32_t* a, const uint32_t* b) {
    asm volatile("mma.sync.aligned.m16n8k16.row.col.f32.bf16.bf16.f32 "
                 "{%0,%1,%2,%3}, {%4,%5,%6,%7}, {%8,%9}, {%0,%1,%2,%3};"
                 : "+f"(d[0]), "+f"(d[1]), "+f"(d[2]), "+f"(d[3])
                 : "r"(a[0]), "r"(a[1]), "r"(a[2]), "r"(a[3]), "r"(b[0]), "r"(b[1]));
}
__device__ __forceinline__ void bf16_split(float v, __nv_bfloat16& hi, __nv_bfloat16& lo) {
    hi = __float2bfloat16(v);
    lo = __float2bfloat16(v - __bfloat162float(hi));
}

// ---------------- K1: backbone hidden h = relu(relu(z@w1+b1)@w2+b2) ----------------
__global__ void __launch_bounds__(64) k_backbone(
    const float* __restrict__ z,
    const float* __restrict__ w1, const float* __restrict__ b1,
    const float* __restrict__ w2, const float* __restrict__ b2,
    int sel)
{
    int b = blockIdx.x, t = threadIdx.x;
    __shared__ float zs[32];
    __shared__ float h1[64];
    if (t < 32) zs[t] = z[b * 32 + t];
    __syncthreads();
    float acc = b1[t];
#pragma unroll
    for (int i = 0; i < 32; i++) acc = fmaf(zs[i], w1[i * 64 + t], acc);
    h1[t] = fmaxf(acc, 0.f);
    __syncthreads();
    float acc2 = b2[t];
#pragma unroll
    for (int i = 0; i < 64; i++) acc2 = fmaf(h1[i], w2[i * 64 + t], acc2);
    float* out = sel ? g_hp : g_hs;
    out[b * 64 + t] = fmaxf(acc2, 0.f);
}

// ---------------- K2: materialize P = h @ w3 + b3 via mma.sync bf16 split ----------------
// C = A(1024x64) @ B(64xN), fp32 accum. C = Ah*Bh + Ah*Bl + Al*Bh (rel err ~1e-5).
// CTA tile 128(M) x 64(N), 256 thr = 8 warps (4 M x 2 N), warp tile 32x32.
// SMEM bf16 tiles with 72-elem (144B) row pitch -> conflict-free ldmatrix.
// Layout (bytes): Ah[128][72]@0, Al@18432, Bh[64][72]@36864, Bl@46080, bias@55296. Total 55552.
__global__ void __launch_bounds__(256) k_mat_mma(
    const float* __restrict__ w3, const float* __restrict__ b3, int N, int sel)
{
    extern __shared__ char smc[];
    const uint32_t A_HI = 0, A_LO = 18432, B_HI = 36864, B_LO = 46080, BIAS = 55296;
    uint32_t sb = smem_u32(smc);
    const float* h = sel ? g_hp : g_hs;
    float* P = sel ? g_pp : g_ps;
    int n0 = blockIdx.x * 64, b0 = blockIdx.y * 128;
    int t = threadIdx.x;
    float* bias_sm = (float*)(smc + BIAS);
    if (t < 64) bias_sm[t] = (n0 + t < N) ? b3[n0 + t] : 0.f;

    // stage A: 128 rows x 32 bf16x2 (hi/lo), pitch 36 words
#pragma unroll
    for (int i = 0; i < 16; i++) {
        int idx = t + 256 * i;
        int r = idx >> 5, kp = idx & 31;
        float2 v = *(const float2*)&h[(size_t)(b0 + r) * 64 + kp * 2];
        __nv_bfloat162 hi, lo;
        bf16_split(v.x, hi.x, lo.x);
        bf16_split(v.y, hi.y, lo.y);
        *(__nv_bfloat162*)(smc + A_HI + (r * 36 + kp) * 4) = hi;
        *(__nv_bfloat162*)(smc + A_LO + (r * 36 + kp) * 4) = lo;
    }
    // stage B: Bt[n][k]; thread: n = t&63, kp range by quarter
    {
        int nl = t & 63, q = t >> 6;
        int n = n0 + nl;
        bool ok = n < N;
#pragma unroll
        for (int j = 0; j < 8; j++) {
            int kp = q * 8 + j;
            float v0 = ok ? w3[(size_t)(2 * kp) * N + n] : 0.f;
            float v1 = ok ? w3[(size_t)(2 * kp + 1) * N + n] : 0.f;
            __nv_bfloat162 hi, lo;
            bf16_split(v0, hi.x, lo.x);
            bf16_split(v1, hi.y, lo.y);
            *(__nv_bfloat162*)(smc + B_HI + (nl * 36 + kp) * 4) = hi;
            *(__nv_bfloat162*)(smc + B_LO + (nl * 36 + kp) * 4) = lo;
        }
    }
    __syncthreads();

    int w = t >> 5, l = t & 31, g = l >> 2, t4 = l & 3;
    int wm = w >> 1, wn = w & 1;
    float acc[2][4][4];
#pragma unroll
    for (int mi = 0; mi < 2; mi++)
#pragma unroll
        for (int ni = 0; ni < 4; ni++)
#pragma unroll
            for (int q = 0; q < 4; q++) acc[mi][ni][q] = 0.f;

    // ldmatrix lane address components
    int a_row_in = (l & 7) + ((l >> 3) & 1) * 8;   // bit3 -> +8 rows
    int a_colsel = (l >> 4) & 1;                   // bit4 -> +16 bytes
    int b_row_in = (l & 7) + ((l >> 4) & 1) * 8;   // bit4 -> +8 rows
    int b_colsel = (l >> 3) & 1;                   // bit3 -> +16 bytes

#pragma unroll
    for (int ks = 0; ks < 4; ks++) {
        int acol = ks * 32 + a_colsel * 16;
        int bcol = ks * 32 + b_colsel * 16;
        uint32_t ah[2][4], al[2][4], bh[4][2], bl[4][2];
#pragma unroll
        for (int mi = 0; mi < 2; mi++) {
            uint32_t off = (uint32_t)((wm * 32 + mi * 16 + a_row_in) * 144 + acol);
            ldm_x4(ah[mi][0], ah[mi][1], ah[mi][2], ah[mi][3], sb + A_HI + off);
            ldm_x4(al[mi][0], al[mi][1], al[mi][2], al[mi][3], sb + A_LO + off);
        }
#pragma unroll
        for (int np = 0; np < 2; np++) {
            uint32_t off = (uint32_t)((wn * 32 + np * 16 + b_row_in) * 144 + bcol);
            ldm_x4(bh[np * 2][0], bh[np * 2][1], bh[np * 2 + 1][0], bh[np * 2 + 1][1],
                   sb + B_HI + off);
            ldm_x4(bl[np * 2][0], bl[np * 2][1], bl[np * 2 + 1][0], bl[np * 2 + 1][1],
                   sb + B_LO + off);
        }
#pragma unroll
        for (int mi = 0; mi < 2; mi++)
#pragma unroll
            for (int ni = 0; ni < 4; ni++) {
                mma_bf16(acc[mi][ni], ah[mi], bh[ni]);
                mma_bf16(acc[mi][ni], ah[mi], bl[ni]);
                mma_bf16(acc[mi][ni], al[mi], bh[ni]);
            }
    }

    // epilogue: float2 stores (cols even, N even -> aligned & in-bounds pairwise)
#pragma unroll
    for (int mi = 0; mi < 2; mi++) {
        int row0 = b0 + wm * 32 + mi * 16 + g;
#pragma unroll
        for (int ni = 0; ni < 4; ni++) {
            int cl = wn * 32 + ni * 8 + t4 * 2;
            int col = n0 + cl;
            if (col < N) {
                float bv0 = bias_sm[cl], bv1 = bias_sm[cl + 1];
                float2 v0 = { acc[mi][ni][0] + bv0, acc[mi][ni][1] + bv1 };
                float2 v1 = { acc[mi][ni][2] + bv0, acc[mi][ni][3] + bv1 };
                *(float2*)&P[(size_t)row0 * N + col] = v0;
                *(float2*)&P[(size_t)(row0 + 8) * N + col] = v1;
            }
        }
    }
}

// ---------------- K3: 20-round enc+GRU recurrence, params cached in SMEM ----------------
__global__ void __launch_bounds__(128) k_recur()
{
    extern __shared__ float sm[];
    int b = blockIdx.x, t = threadIdx.x;
    int w = t >> 5, l = t & 31;
    const float* ps = g_ps + (size_t)b * NS;
    const float* pp = g_pp + (size_t)b * NP;
    for (int i = t; i < 784; i += 128)
        ((float4*)sm)[i] = ((const float4*)ps)[i];
    for (int i = t; i < 1560; i += 128)
        ((float4*)(sm + 3136))[i] = *(const float4*)(ps + 30064 + i * 4);
    for (int i = t; i < 784; i += 128)
        ((float4*)(sm + 9376))[i] = ((const float4*)pp)[i];
    for (int i = t; i < 1560; i += 128)
        ((float4*)(sm + 12512))[i] = *(const float4*)(pp + 4324 + i * 4);
    if (t < 32) {
        sm[18752 + t] = ps[36304 + t];   // z0_init
        sm[18784 + t] = pp[10564 + t];   // za0_init
    }
    if (t < 64) sm[18880 + t] = 0.f;
    __syncthreads();

    float* ein  = sm + 18816;
    float* hbuf = sm + 18880;
    float* hold = sm + 18944;
    float* ebuf = sm + 19008;
    float* rhb  = sm + 19072;
    const int base = w * 9376;
    float* Yout = (w ? g_Yp : g_Ys) + (size_t)b * 640;

    for (int r = 0; r < 20; r++) {
        int r5 = r % 5;
        if (t < 64) {
            float zin;
            if (r == 0 || r5 == 1)      zin = sm[18752 + w * 32 + l];
            else if (r5 == 0)           zin = hold[w * 32 + l];
            else                        zin = hbuf[w * 32 + l];
            ein[w * 32 + l] = zin;
        }
        __syncthreads();

        if (t < 64) {
            float a0 = 0, a1 = 0, a2 = 0, a3 = 0;
#pragma unroll
            for (int i = 0; i < 64; i += 4) {
                a0 = fmaf(ein[i],     sm[base + (i)     * 32 + l], a0);
                a1 = fmaf(ein[i + 1], sm[base + (i + 1) * 32 + l], a1);
                a2 = fmaf(ein[i + 2], sm[base + (i + 2) * 32 + l], a2);
                a3 = fmaf(ein[i + 3], sm[base + (i + 3) * 32 + l], a3);
            }
            float e1 = fmaxf(sm[base + 2048 + l] + ((a0 + a1) + (a2 + a3)), 0.f);
            ebuf[w * 32 + l] = e1;
            __syncwarp();

            a0 = a1 = a2 = a3 = 0;
#pragma unroll
            for (int i = 0; i < 32; i += 4) {
                a0 = fmaf(ebuf[w * 32 + i],     sm[base + 2080 + (i)     * 32 + l], a0);
                a1 = fmaf(ebuf[w * 32 + i + 1], sm[base + 2080 + (i + 1) * 32 + l], a1);
                a2 = fmaf(ebuf[w * 32 + i + 2], sm[base + 2080 + (i + 2) * 32 + l], a2);
                a3 = fmaf(ebuf[w * 32 + i + 3], sm[base + 2080 + (i + 3) * 32 + l], a3);
            }
            float e2 = sm[base + 3104 + l] + ((a0 + a1) + (a2 + a3));
            __syncwarp();
            ebuf[w * 32 + l] = e2;
            __syncwarp();

            float gz = sm[base + 9280 + l];
            float gr = sm[base + 9280 + 32 + l];
            float gh = sm[base + 9280 + 64 + l];
            float hz = 0.f, hr = 0.f;
#pragma unroll
            for (int i = 0; i < 32; i++) {
                float e  = ebuf[w * 32 + i];
                float hv = hbuf[w * 32 + i];
                gz = fmaf(e,  sm[base + 3136 + i * 96 + l],      gz);
                gr = fmaf(e,  sm[base + 3136 + i * 96 + 32 + l], gr);
                gh = fmaf(e,  sm[base + 3136 + i * 96 + 64 + l], gh);
                hz = fmaf(hv, sm[base + 6208 + i * 96 + l],      hz);
                hr = fmaf(hv, sm[base + 6208 + i * 96 + 32 + l], hr);
            }
            float zgate = 1.f / (1.f + expf(-(gz + hz)));
            float rgate = 1.f / (1.f + expf(-(gr + hr)));
            float hl = hbuf[w * 32 + l];
            rhb[w * 32 + l] = rgate * hl;
            __syncwarp();
            float hh3 = 0.f;
#pragma unroll
            for (int i = 0; i < 32; i++)
                hh3 = fmaf(rhb[w * 32 + i], sm[base + 6208 + i * 96 + 64 + l], hh3);
            float hh = tanhf(gh + hh3);
            float hnew = fmaf(zgate, hl - hh, hh);
            __syncwarp();
            hbuf[w * 32 + l] = hnew;
            if (r5 == 0) hold[w * 32 + l] = hnew;
            Yout[r * 32 + l] = hnew;
        }
        __syncthreads();
    }
}

// ---------------- K4: dec1 readouts (batched) ----------------
__global__ void __launch_bounds__(64) k_dec()
{
    int b = blockIdx.x, t = threadIdx.x;
    int w = t >> 5, l = t & 31;
    const float* ps = g_ps + (size_t)b * NS;
    const float* pp = g_pp + (size_t)b * NP;
    __shared__ float sW0[1056];
    __shared__ float sW1[1056];
    __shared__ float sW2[132];
    __shared__ float stmp[32];
    for (int i = t; i < 1056; i += 64) { sW0[i] = ps[3136 + i]; sW1[i] = pp[3136 + i]; }
    for (int i = t; i < 132; i += 64) sW2[i] = pp[4192 + i];
    __syncthreads();

    if (w == 0) {
        for (int m = 0; m < 16; m++) {
            int r = (m >> 2) * 5 + 1 + (m & 3);
            const float* y = g_Ys + (size_t)b * 640 + r * 32;
            float acc = sW0[1024 + l];
#pragma unroll
            for (int i = 0; i < 32; i++) acc = fmaf(y[i], sW0[i * 32 + l], acc);
            g_D1s[(size_t)b * 512 + m * 32 + l] = fmaxf(acc, 0.f);
        }
    } else {
        for (int r = 0; r < 20; r++) {
            const float* y = g_Yp + (size_t)b * 640 + r * 32;
            float acc = sW1[1024 + l];
#pragma unroll
            for (int i = 0; i < 32; i++) acc = fmaf(y[i], sW1[i * 32 + l], acc);
            stmp[l] = fmaxf(acc, 0.f);
            __syncwarp();
            if (l < 4) {
                float a = sW2[128 + l];
#pragma unroll
                for (int i = 0; i < 32; i++) a = fmaf(stmp[i], sW2[i * 4 + l], a);
                g_av[(size_t)b * 80 + r * 4 + l] = a;
            }
            __syncwarp();
        }
    }
}

// ---------------- K5: x_hat = D1s(16x32) @ W2f(32x784) + bias, per batch ----------------
__global__ void __launch_bounds__(256) k_xhat()
{
    int b = blockIdx.x, tid = threadIdx.x;
    const float* ps = g_ps + (size_t)b * NS;
    __shared__ float d1[512];
    for (int i = tid; i < 512; i += 256) d1[i] = g_D1s[(size_t)b * 512 + i];
    __syncthreads();

    float acc[4][16];
#pragma unroll
    for (int q = 0; q < 4; q++) {
        int o = tid + 256 * q;
        float bias = (o < 784) ? ps[29280 + o] : 0.f;
#pragma unroll
        for (int m = 0; m < 16; m++) acc[q][m] = bias;
    }
#pragma unroll 4
    for (int j = 0; j < 32; j++) {
        const float* wrow = ps + 4192 + j * 784;
        float w0 = wrow[tid];
        float w1 = wrow[tid + 256];
        float w2 = wrow[tid + 512];
        float w3v = (tid < 16) ? wrow[tid + 768] : 0.f;
#pragma unroll
        for (int m = 0; m < 16; m++) {
            float dv = d1[m * 32 + j];
            acc[0][m] = fmaf(dv, w0, acc[0][m]);
            acc[1][m] = fmaf(dv, w1, acc[1][m]);
            acc[2][m] = fmaf(dv, w2, acc[2][m]);
            acc[3][m] = fmaf(dv, w3v, acc[3][m]);
        }
    }
    float* xh = g_xh + (size_t)b * 12544;
#pragma unroll
    for (int q = 0; q < 4; q++) {
        int o = tid + 256 * q;
        if (o < 784) {
#pragma unroll
            for (int m = 0; m < 16; m++) xh[m * 784 + o] = acc[q][m];
        }
    }
}

// ---------------- K6: inner + outer bilinear composite ----------------
__device__ __forceinline__ float bsample(const float* img, float a0, float a1,
                                         float a2, float a3, int i, int j)
{
    float sx = a0 + 1.f, sy = a1 + 1.f;
    float gx = -1.f + j * (2.f / 27.f);
    float gy = -1.f + i * (2.f / 27.f);
    float px = (fmaf(sx, gx, a2) + 1.f) * 13.5f;
    float py = (fmaf(sy, gy, a3) + 1.f) * 13.5f;
    float x0 = floorf(px), y0 = floorf(py);
    float wx = px - x0, wy = py - y0;
    int xi = (int)x0, yi = (int)y0;
    float v00 = (yi >= 0 && yi < 28 && xi >= 0 && xi < 28)         ? img[yi * 28 + xi]           : 0.f;
    float v01 = (yi >= 0 && yi < 28 && xi + 1 >= 0 && xi + 1 < 28) ? img[yi * 28 + xi + 1]       : 0.f;
    float v10 = (yi + 1 >= 0 && yi + 1 < 28 && xi >= 0 && xi < 28) ? img[(yi + 1) * 28 + xi]     : 0.f;
    float v11 = (yi + 1 >= 0 && yi + 1 < 28 && xi + 1 >= 0 && xi + 1 < 28) ? img[(yi + 1) * 28 + xi + 1] : 0.f;
    return v00 * (1.f - wx) * (1.f - wy) + v01 * wx * (1.f - wy)
         + v10 * (1.f - wx) * wy + v11 * wx * wy;
}

__global__ void __launch_bounds__(256) k_compose(float* __restrict__ out)
{
    extern __shared__ float s[];
    float* xh = s;            // 12544
    float* Oi = s + 12544;    // 3136
    float* av = s + 15680;    // 80
    int b = blockIdx.x, tid = threadIdx.x;
    const float* gxh = g_xh + (size_t)b * 12544;
    for (int i = tid; i < 3136; i += 256)
        ((float4*)xh)[i] = ((const float4*)gxh)[i];
    if (tid < 80) av[tid] = g_av[(size_t)b * 80 + tid];
    __syncthreads();

    for (int tt = 0; tt < 4; tt++) {
        for (int p = tid; p < 784; p += 256) {
            int i = p / 28, j = p % 28;
            float acc = 0.f;
#pragma unroll
            for (int u = 0; u < 4; u++) {
                const float* ai = av + (5 * tt + 1 + u) * 4;
                acc += bsample(xh + (4 * tt + u) * 784, ai[0], ai[1], ai[2], ai[3], i, j);
            }
            Oi[tt * 784 + p] = acc;
        }
    }
    __syncthreads();
    for (int p = tid; p < 784; p += 256) {
        int i = p / 28, j = p % 28;
        float acc = 0.f;
#pragma unroll
        for (int tt = 0; tt < 4; tt++) {
            const float* ao = av + 5 * tt * 4;
            acc += bsample(Oi + tt * 784, ao[0], ao[1], ao[2], ao[3], i, j);
        }
        out[(size_t)b * 784 + p] = acc;
    }
}

// ---------------- launch ----------------
extern "C" void kernel_launch(void* const* d_in, const int* in_sizes, int n_in,
                              void* d_out, int out_size)
{
    (void)in_sizes; (void)n_in; (void)out_size;
    const float* z    = (const float*)d_in[1];
    const float* s_w1 = (const float*)d_in[2];
    const float* s_b1 = (const float*)d_in[3];
    const float* s_w2 = (const float*)d_in[4];
    const float* s_b2 = (const float*)d_in[5];
    const float* s_w3 = (const float*)d_in[6];
    const float* s_b3 = (const float*)d_in[7];
    const float* p_w1 = (const float*)d_in[8];
    const float* p_b1 = (const float*)d_in[9];
    const float* p_w2 = (const float*)d_in[10];
    const float* p_b2 = (const float*)d_in[11];
    const float* p_w3 = (const float*)d_in[12];
    const float* p_b3 = (const float*)d_in[13];
    float* out = (float*)d_out;

    cudaFuncSetAttribute(k_mat_mma, cudaFuncAttributeMaxDynamicSharedMemorySize, 55552);
    cudaFuncSetAttribute(k_recur, cudaFuncAttributeMaxDynamicSharedMemorySize, 76544);
    cudaFuncSetAttribute(k_compose, cudaFuncAttributeMaxDynamicSharedMemorySize, 63040);

    k_backbone<<<BSZ, 64>>>(z, s_w1, s_b1, s_w2, s_b2, 0);
    k_backbone<<<BSZ, 64>>>(z, p_w1, p_b1, p_w2, p_b2, 1);
    k_mat_mma<<<dim3((NS + 63) / 64, BSZ / 128), 256, 55552>>>(s_w3, s_b3, NS, 0);
    k_mat_mma<<<dim3((NP + 63) / 64, BSZ / 128), 256, 55552>>>(p_w3, p_b3, NP, 1);
    k_recur<<<BSZ, 128, 76544>>>();
    k_dec<<<BSZ, 64>>>();
    k_xhat<<<BSZ, 256>>>();
    k_compose<<<BSZ, 256, 63040>>>(out);
}